// round 14
// baseline (speedup 1.0000x reference)
#include <cuda_runtime.h>
#include <cuda_fp16.h>
#include <math.h>
#include <cstdint>

// Problem constants
#define BB 64
#define TT 256
#define CC 384
#define HH 6
#define HS 64
#define MM (BB * TT)          // 16384
#define NQKV (3 * CC)         // 1152
#define CF (4 * CC)           // 1536

// ---------------- scratch (static __device__, no allocs) ----------------
__device__ __half g_h[MM * CC];       // ln output (half, GEMM A input)
__device__ __half g_qkvh[MM * NQKV];  // packed Q|K|V (half)
__device__ __half g_o[MM * CC];       // attention output (half)
__device__ float  g_x1[MM * CC];      // first residual (f32)
__device__ __half g_f1[MM * CF];      // FFN hidden (half)
// transposed (N-major, K-contig) fp16 weights
__device__ __half g_WqkvT[NQKV * CC];
__device__ __half g_WprojT[CC * CC];
__device__ __half g_W1T[CF * CC];
__device__ __half g_W2T[CC * CF];
__device__ float  g_bqkv[NQKV];

__device__ __forceinline__ uint32_t smem_u32(const void* p) {
    uint32_t a;
    asm("{ .reg .u64 t; cvta.to.shared.u64 t, %1; cvt.u32.u64 %0, t; }" : "=r"(a) : "l"(p));
    return a;
}
__device__ __forceinline__ void grid_dep_sync() {
#if defined(__CUDA_ARCH__) && __CUDA_ARCH__ >= 900
    cudaGridDependencySynchronize();
#endif
}
__device__ __forceinline__ uint32_t h2u(__half2 v) {
    return *(uint32_t*)&v;
}

// ---------------- fused pack (all 4 weights + qkv bias) + LN1, one kernel ----------
#define N_QKVW (NQKV * CC)            // 442368
#define N_PROJ (CC * CC)              // 147456
#define N_W1   (CC * CF)              // 589824
#define N_W2   (CF * CC)              // 589824
#define OFF_PROJ N_QKVW
#define OFF_W1   (OFF_PROJ + N_PROJ)
#define OFF_W2   (OFF_W1 + N_W1)
#define N_PACK   (OFF_W2 + N_W2)      // 1769472
#define PACK_BLOCKS (N_PACK / 256)    // 6912
#define LN_BLOCKS (MM / 8)            // 2048

__device__ __forceinline__ void ln_row(const float* __restrict__ x,
                                       const float* __restrict__ w,
                                       const float* __restrict__ b,
                                       __half* __restrict__ y, int row, int lane) {
    const float4* xr = (const float4*)(x + (size_t)row * CC);
    float4 v0 = xr[lane], v1 = xr[lane + 32], v2 = xr[lane + 64];
    float s = v0.x + v0.y + v0.z + v0.w + v1.x + v1.y + v1.z + v1.w
            + v2.x + v2.y + v2.z + v2.w;
    float ss = v0.x * v0.x + v0.y * v0.y + v0.z * v0.z + v0.w * v0.w
             + v1.x * v1.x + v1.y * v1.y + v1.z * v1.z + v1.w * v1.w
             + v2.x * v2.x + v2.y * v2.y + v2.z * v2.z + v2.w * v2.w;
    #pragma unroll
    for (int o = 16; o > 0; o >>= 1) {
        s += __shfl_xor_sync(0xffffffffu, s, o);
        ss += __shfl_xor_sync(0xffffffffu, ss, o);
    }
    float mean = s * (1.0f / CC);
    float inv = rsqrtf(ss * (1.0f / CC) - mean * mean + 1e-5f);
    const float4* w4 = (const float4*)w;
    const float4* b4 = (const float4*)b;
    __half* yr = y + (size_t)row * CC;
    float4 vv[3] = {v0, v1, v2};
    #pragma unroll
    for (int j = 0; j < 3; j++) {
        float4 ww = w4[j * 32 + lane];
        float4 bb = b4[j * 32 + lane];
        float o0 = (vv[j].x - mean) * inv * ww.x + bb.x;
        float o1 = (vv[j].y - mean) * inv * ww.y + bb.y;
        float o2 = (vv[j].z - mean) * inv * ww.z + bb.z;
        float o3 = (vv[j].w - mean) * inv * ww.w + bb.w;
        uint2 pk;
        pk.x = h2u(__floats2half2_rn(o0, o1));
        pk.y = h2u(__floats2half2_rn(o2, o3));
        *(uint2*)&yr[j * 128 + 4 * lane] = pk;
    }
}

__global__ __launch_bounds__(256) void pack_ln_kernel(
        const float* __restrict__ Wq, const float* __restrict__ Wk,
        const float* __restrict__ Wv, const float* __restrict__ bq,
        const float* __restrict__ bk, const float* __restrict__ bv,
        const float* __restrict__ Wproj, const float* __restrict__ W1,
        const float* __restrict__ W2,
        const float* __restrict__ x, const float* __restrict__ ln1w,
        const float* __restrict__ ln1b, __half* __restrict__ hout) {
    int bid = blockIdx.x;
    if (bid < PACK_BLOCKS) {
        int i = bid * 256 + threadIdx.x;
        if (i < N_QKVW) {
            int n = i / CC, k = i % CC;
            int s2 = n / CC;
            int nn = n % CC;
            const float* src = (s2 == 0) ? Wq : (s2 == 1) ? Wk : Wv;
            g_WqkvT[i] = __float2half_rn(src[(nn / HS) * (CC * HS) + k * HS + (nn % HS)]);
        } else if (i < OFF_W1) {
            int j = i - OFF_PROJ;
            int n = j / CC, k = j % CC;
            g_WprojT[j] = __float2half_rn(Wproj[(size_t)k * CC + n]);
        } else if (i < OFF_W2) {
            int j = i - OFF_W1;
            int n = j / CC, k = j % CC;
            g_W1T[j] = __float2half_rn(W1[(size_t)k * CF + n]);
        } else if (i < N_PACK) {
            int j = i - OFF_W2;
            int n = j / CF, k = j % CF;
            g_W2T[j] = __float2half_rn(W2[(size_t)k * CC + n]);
        }
        if (i < NQKV) {
            int s2 = i / CC;
            int nn = i % CC;
            const float* sb = (s2 == 0) ? bq : (s2 == 1) ? bk : bv;
            g_bqkv[i] = sb[nn];
        }
    } else {
        int wid = threadIdx.x >> 5, lane = threadIdx.x & 31;
        int row = (bid - PACK_BLOCKS) * 8 + wid;
        ln_row(x, ln1w, ln1b, hout, row, lane);
    }
}

// ---------------- LayerNorm (LN2): one warp per row ----------------
__global__ __launch_bounds__(256) void ln_kernel(const float* __restrict__ x,
                                                 const float* __restrict__ w,
                                                 const float* __restrict__ b,
                                                 __half* __restrict__ y) {
    grid_dep_sync();
    int wid = threadIdx.x >> 5, lane = threadIdx.x & 31;
    int row = blockIdx.x * 8 + wid;
    ln_row(x, w, b, y, row, lane);
}

// ---------------- fp16 mma helpers ----------------
__device__ __forceinline__ void mma_f16(float* c, const uint32_t* a, const uint32_t* b) {
    asm volatile(
        "mma.sync.aligned.m16n8k16.row.col.f32.f16.f16.f32 "
        "{%0,%1,%2,%3}, {%4,%5,%6,%7}, {%8,%9}, {%0,%1,%2,%3};"
        : "+f"(c[0]), "+f"(c[1]), "+f"(c[2]), "+f"(c[3])
        : "r"(a[0]), "r"(a[1]), "r"(a[2]), "r"(a[3]), "r"(b[0]), "r"(b[1]));
}

__device__ __forceinline__ void cp16(uint32_t dst, const void* src) {
    asm volatile("cp.async.cg.shared.global [%0], [%1], 16;" :: "r"(dst), "l"(src));
}
__device__ __forceinline__ void ldsm4(uint32_t* r, uint32_t addr) {
    asm volatile("ldmatrix.sync.aligned.m8n8.x4.shared.b16 {%0,%1,%2,%3}, [%4];"
        : "=r"(r[0]), "=r"(r[1]), "=r"(r[2]), "=r"(r[3]) : "r"(addr));
}
__device__ __forceinline__ void ldsm4t(uint32_t* r, uint32_t addr) {
    asm volatile("ldmatrix.sync.aligned.m8n8.x4.trans.shared.b16 {%0,%1,%2,%3}, [%4];"
        : "=r"(r[0]), "=r"(r[1]), "=r"(r[2]), "=r"(r[3]) : "r"(addr));
}

// ---------------- fp16 mma.sync GEMM: 3-stage ring, 1 sync/chunk, 2 CTA/SM ---------
// C[M,N] = A[M,K] @ Bt[N,K]^T + bias ; MODE 0 bias, 1 bias+residual, 2 gelu(bias)
// CTA tile 128x128, 8 warps (2M x 4N), warp 64x32, K-chunk 64 halves (128B rows).
// MODE 1 extra: during the LAST chunk's compute, the 128x128 f32 residual tile is
// cp.async-prefetched into ring buffers 0+1 (free because nc % 3 == 0 for both
// MODE-1 GEMMs: K=384 -> nc=6, K=1536 -> nc=24), and the epilogue reads it from smem.
#define STG_A 16384                    // 128 rows * 128B
#define STG_T 32768                    // A + B per stage
#define SMEM_TOTAL_G (3 * STG_T)       // 98304 (3 stages)

template <int MODE, int OUTH>
__global__ __launch_bounds__(256, 2) void mma_gemm16(const __half* __restrict__ A,
                                                     const __half* __restrict__ Bt,
                                                     const float* __restrict__ bias,
                                                     const float* __restrict__ Rres,
                                                     void* __restrict__ Cout,
                                                     int M, int N, int K) {
    extern __shared__ __align__(16) char smem[];
    int tid = threadIdx.x;
    int lane = tid & 31, wid = tid >> 5;
    int warpM = wid & 1, warpN = wid >> 1;
    int g = lane >> 2, tg = lane & 3;
    int row0 = blockIdx.y * 128, col0 = blockIdx.x * 128;

    uint32_t sbase = smem_u32(smem);

    int cRow = tid >> 3;               // 0..31
    int cGrp = tid & 7;                // 16B group
    const __half* Ag = A + (size_t)(row0 + cRow) * K + cGrp * 8;
    const __half* Bg = Bt + (size_t)(col0 + cRow) * K + cGrp * 8;

    auto issue = [&](int c, int buf) {
        uint32_t dA = sbase + (uint32_t)buf * STG_T;
        uint32_t dB = dA + STG_A;
        #pragma unroll
        for (int pass = 0; pass < 4; pass++) {
            int row = cRow + pass * 32;
            uint32_t off = (uint32_t)row * 128 + (uint32_t)((cGrp ^ (row & 7)) << 4);
            cp16(dA + off, Ag + (size_t)(pass * 32) * K + c * 64);
            cp16(dB + off, Bg + (size_t)(pass * 32) * K + c * 64);
        }
        asm volatile("cp.async.commit_group;" ::: "memory");
    };

    int lr = lane & 7;
    int lh = (lane >> 3) & 1;
    uint32_t lk = (uint32_t)(lane >> 4);
    uint32_t aRowOff[4], aXor[4];
    #pragma unroll
    for (int mi = 0; mi < 4; mi++) {
        int row = warpM * 64 + mi * 16 + lr + lh * 8;
        aRowOff[mi] = (uint32_t)row * 128;
        aXor[mi] = (uint32_t)(row & 7);
    }
    uint32_t bRowOff[2], bXor[2];
    #pragma unroll
    for (int p = 0; p < 2; p++) {
        int row = warpN * 32 + p * 16 + lr + lh * 8;
        bRowOff[p] = (uint32_t)row * 128;
        bXor[p] = (uint32_t)(row & 7);
    }

    float acc[4][4][4];
    #pragma unroll
    for (int mi = 0; mi < 4; mi++)
        #pragma unroll
        for (int ni = 0; ni < 4; ni++)
            #pragma unroll
            for (int r = 0; r < 4; r++) acc[mi][ni][r] = 0.0f;

    grid_dep_sync();

    int nc = K / 64;
    issue(0, 0);
    if (nc > 1) issue(1, 1);
    if (nc > 2) issue(2, 2);

    for (int c = 0; c < nc; c++) {
        if (c + 1 < nc)
            asm volatile("cp.async.wait_group 1;" ::: "memory");
        else
            asm volatile("cp.async.wait_group 0;" ::: "memory");
        __syncthreads();
        if (c >= 1 && c + 2 < nc) issue(c + 2, (c + 2) % 3);
        if (MODE == 1 && c == nc - 1) {
            // prefetch residual tile (128x128 f32 = 64KB) into free buffers 0+1
            int rrow = tid >> 1;                 // 0..127
            int rhalf = (tid & 1) * 64;          // float offset within row
            const float* Rp = Rres + (size_t)(row0 + rrow) * N + col0 + rhalf;
            uint32_t dR = sbase + (uint32_t)rrow * 512 + (uint32_t)rhalf * 4;
            #pragma unroll
            for (int j = 0; j < 16; j++)
                cp16(dR + j * 16, Rp + j * 4);
            asm volatile("cp.async.commit_group;" ::: "memory");
        }

        uint32_t sA = sbase + (uint32_t)(c % 3) * STG_T;
        uint32_t sB = sA + STG_A;

        #pragma unroll
        for (int ks = 0; ks < 4; ks++) {
            uint32_t kg = (uint32_t)(ks * 2) + lk;
            uint32_t afr[4][4], breg[2][4];
            #pragma unroll
            for (int mi = 0; mi < 4; mi++)
                ldsm4(afr[mi], sA + aRowOff[mi] + ((kg ^ aXor[mi]) << 4));
            #pragma unroll
            for (int p = 0; p < 2; p++)
                ldsm4(breg[p], sB + bRowOff[p] + ((kg ^ bXor[p]) << 4));
            #pragma unroll
            for (int mi = 0; mi < 4; mi++) {
                #pragma unroll
                for (int p = 0; p < 2; p++) {
                    uint32_t b0[2] = {breg[p][0], breg[p][2]};
                    uint32_t b1[2] = {breg[p][1], breg[p][3]};
                    mma_f16(acc[mi][2 * p], afr[mi], b0);
                    mma_f16(acc[mi][2 * p + 1], afr[mi], b1);
                }
            }
        }
    }

    if (MODE == 1) {
        asm volatile("cp.async.wait_group 0;" ::: "memory");
        __syncthreads();
    }

    // epilogue
    #pragma unroll
    for (int mi = 0; mi < 4; mi++) {
        #pragma unroll
        for (int ni = 0; ni < 4; ni++) {
            int rA = row0 + warpM * 64 + mi * 16 + g;
            int cA = col0 + warpN * 32 + ni * 8 + tg * 2;
            float b0 = bias[cA], b1 = bias[cA + 1];
            #pragma unroll
            for (int half = 0; half < 2; half++) {
                int r = rA + half * 8;
                float o0 = acc[mi][ni][half * 2 + 0] + b0;
                float o1 = acc[mi][ni][half * 2 + 1] + b1;
                size_t idx = (size_t)r * N + cA;
                if (MODE == 1) {
                    int rl = warpM * 64 + mi * 16 + g + half * 8;
                    int cl = warpN * 32 + ni * 8 + tg * 2;
                    const float2 rr = *(const float2*)(smem + (size_t)rl * 512 + cl * 4);
                    o0 += rr.x; o1 += rr.y;
                }
                if (MODE == 2) {
                    o0 = 0.5f * o0 * (1.0f + erff(o0 * 0.70710678118654752f));
                    o1 = 0.5f * o1 * (1.0f + erff(o1 * 0.70710678118654752f));
                }
                if (OUTH) {
                    *(__half2*)((__half*)Cout + idx) = __floats2half2_rn(o0, o1);
                } else {
                    *(float2*)((float*)Cout + idx) = make_float2(o0, o1);
                }
            }
        }
    }
}

// ---------------- flash attention: balanced q-row pairing, ldmatrix, 2 CTA/SM ------
#define ATT_STG 32768                          // 256 rows * 128B
#define ATT_SMEM (2 * ATT_STG)                 // 65536

__global__ __launch_bounds__(256, 2) void attn_mma(const __half* __restrict__ qkv,
                                                   __half* __restrict__ o) {
    extern __shared__ __align__(16) char smh[];
    uint32_t sK = smem_u32(smh);
    uint32_t sV = sK + ATT_STG;
    int idx = blockIdx.x;
    int sel = idx & 1;
    int h = (idx >> 1) % HH;
    int b = idx / (2 * HH);
    size_t base = (size_t)b * TT * NQKV + (size_t)h * HS;
    int tid = threadIdx.x;
    int wid = tid >> 5, lane = tid & 31;
    int g = lane >> 2, tg = lane & 3;

    int glo = sel ? 1 : 0;
    int ghi = sel ? 2 : 3;
    int nkeys = (ghi + 1) * 64;            // 256 or 192
    int grp = (wid < 4) ? glo : ghi;
    int qbase = grp * 64 + (wid & 3) * 16;

    grid_dep_sync();

    // cp.async fill of K and V (swizzled rows)
    {
        int cRow = tid >> 3, cGrp = tid & 7;
        const __half* Kg = qkv + base + CC + (size_t)cRow * NQKV + cGrp * 8;
        const __half* Vg = qkv + base + 2 * CC + (size_t)cRow * NQKV + cGrp * 8;
        int np = nkeys / 32;
        for (int pass = 0; pass < np; pass++) {
            int row = cRow + pass * 32;
            uint32_t off = (uint32_t)row * 128 + (uint32_t)((cGrp ^ (row & 7)) << 4);
            cp16(sK + off, Kg + (size_t)(pass * 32) * NQKV);
            cp16(sV + off, Vg + (size_t)(pass * 32) * NQKV);
        }
        asm volatile("cp.async.commit_group;" ::: "memory");
    }

    // Q fragments from gmem (overlaps with cp.async)
    uint32_t qf[4][4];
    const __half* qp = &qkv[base + (size_t)qbase * NQKV];
    #pragma unroll
    for (int ks = 0; ks < 4; ks++) {
        int d0 = ks * 16;
        qf[ks][0] = *(const uint32_t*)&qp[(size_t)g * NQKV + d0 + 2 * tg];
        qf[ks][1] = *(const uint32_t*)&qp[(size_t)(g + 8) * NQKV + d0 + 2 * tg];
        qf[ks][2] = *(const uint32_t*)&qp[(size_t)g * NQKV + d0 + 8 + 2 * tg];
        qf[ks][3] = *(const uint32_t*)&qp[(size_t)(g + 8) * NQKV + d0 + 8 + 2 * tg];
    }

    int lr = lane & 7;
    int lh = (lane >> 3) & 1;
    uint32_t lk = (uint32_t)(lane >> 4);
    int kRowLoc = lr + lh * 8;
    int vRowLoc = lr + lh * 8;

    asm volatile("cp.async.wait_group 0;" ::: "memory");
    __syncthreads();

    float Oa[8][4];
    #pragma unroll
    for (int nb = 0; nb < 8; nb++)
        #pragma unroll
        for (int j = 0; j < 4; j++) Oa[nb][j] = 0.0f;
    float m0 = -1e30f, m1 = -1e30f, l0 = 0.0f, l1 = 0.0f;

    int ktmax = (qbase + 15) >> 6;
    for (int kt = 0; kt <= ktmax; kt++) {
        float S[8][4];
        #pragma unroll
        for (int nb = 0; nb < 8; nb++)
            #pragma unroll
            for (int j = 0; j < 4; j++) S[nb][j] = 0.0f;

        // S = Q @ K^T
        #pragma unroll
        for (int ks = 0; ks < 4; ks++) {
            uint32_t kg = (uint32_t)(ks * 2) + lk;
            #pragma unroll
            for (int p = 0; p < 4; p++) {
                int row = kt * 64 + p * 16 + kRowLoc;
                uint32_t br[4];
                ldsm4(br, sK + (uint32_t)row * 128 + ((kg ^ (uint32_t)(row & 7)) << 4));
                uint32_t b0[2] = {br[0], br[2]};
                uint32_t b1[2] = {br[1], br[3]};
                mma_f16(S[2 * p], qf[ks], b0);
                mma_f16(S[2 * p + 1], qf[ks], b1);
            }
        }
        #pragma unroll
        for (int nb = 0; nb < 8; nb++)
            #pragma unroll
            for (int j = 0; j < 4; j++) S[nb][j] *= 0.125f;
        if (kt == ktmax) {
            int r0 = qbase + g, r1 = r0 + 8;
            #pragma unroll
            for (int nb = 0; nb < 8; nb++) {
                int col = kt * 64 + nb * 8 + 2 * tg;
                if (col > r0)     S[nb][0] = -1e30f;
                if (col + 1 > r0) S[nb][1] = -1e30f;
                if (col > r1)     S[nb][2] = -1e30f;
                if (col + 1 > r1) S[nb][3] = -1e30f;
            }
        }
        float tm0 = -1e30f, tm1 = -1e30f;
        #pragma unroll
        for (int nb = 0; nb < 8; nb++) {
            tm0 = fmaxf(tm0, fmaxf(S[nb][0], S[nb][1]));
            tm1 = fmaxf(tm1, fmaxf(S[nb][2], S[nb][3]));
        }
        tm0 = fmaxf(tm0, __shfl_xor_sync(0xffffffffu, tm0, 1));
        tm0 = fmaxf(tm0, __shfl_xor_sync(0xffffffffu, tm0, 2));
        tm1 = fmaxf(tm1, __shfl_xor_sync(0xffffffffu, tm1, 1));
        tm1 = fmaxf(tm1, __shfl_xor_sync(0xffffffffu, tm1, 2));
        float mn0 = fmaxf(m0, tm0), mn1 = fmaxf(m1, tm1);
        float sc0 = __expf(m0 - mn0), sc1 = __expf(m1 - mn1);
        float ts0 = 0.0f, ts1 = 0.0f;
        #pragma unroll
        for (int nb = 0; nb < 8; nb++) {
            S[nb][0] = __expf(S[nb][0] - mn0);
            S[nb][1] = __expf(S[nb][1] - mn0);
            S[nb][2] = __expf(S[nb][2] - mn1);
            S[nb][3] = __expf(S[nb][3] - mn1);
            ts0 += S[nb][0] + S[nb][1];
            ts1 += S[nb][2] + S[nb][3];
        }
        ts0 += __shfl_xor_sync(0xffffffffu, ts0, 1);
        ts0 += __shfl_xor_sync(0xffffffffu, ts0, 2);
        ts1 += __shfl_xor_sync(0xffffffffu, ts1, 1);
        ts1 += __shfl_xor_sync(0xffffffffu, ts1, 2);
        l0 = l0 * sc0 + ts0;
        l1 = l1 * sc1 + ts1;
        m0 = mn0; m1 = mn1;
        #pragma unroll
        for (int nb = 0; nb < 8; nb++) {
            Oa[nb][0] *= sc0; Oa[nb][1] *= sc0;
            Oa[nb][2] *= sc1; Oa[nb][3] *= sc1;
        }
        // O += P @ V (ldmatrix.trans on V rows)
        #pragma unroll
        for (int ks = 0; ks < 4; ks++) {
            uint32_t ap[4];
            ap[0] = h2u(__floats2half2_rn(S[2 * ks][0], S[2 * ks][1]));
            ap[1] = h2u(__floats2half2_rn(S[2 * ks][2], S[2 * ks][3]));
            ap[2] = h2u(__floats2half2_rn(S[2 * ks + 1][0], S[2 * ks + 1][1]));
            ap[3] = h2u(__floats2half2_rn(S[2 * ks + 1][2], S[2 * ks + 1][3]));
            int krow = kt * 64 + ks * 16 + vRowLoc;
            uint32_t rbase = sV + (uint32_t)krow * 128;
            uint32_t rx = (uint32_t)(krow & 7);
            #pragma unroll
            for (int dp = 0; dp < 4; dp++) {
                uint32_t cg = (uint32_t)(dp * 2) + lk;
                uint32_t vr[4];
                ldsm4t(vr, rbase + ((cg ^ rx) << 4));
                uint32_t b0[2] = {vr[0], vr[1]};
                uint32_t b1[2] = {vr[2], vr[3]};
                mma_f16(Oa[2 * dp], ap, b0);
                mma_f16(Oa[2 * dp + 1], ap, b1);
            }
        }
    }

    float inv0 = 1.0f / l0, inv1 = 1.0f / l1;
    __half* op = o + ((size_t)(b * TT + qbase + g) * CC + h * HS);
    __half* op1 = op + 8 * CC;
    #pragma unroll
    for (int nb = 0; nb < 8; nb++) {
        *(__half2*)&op[nb * 8 + 2 * tg]  = __floats2half2_rn(Oa[nb][0] * inv0, Oa[nb][1] * inv0);
        *(__half2*)&op1[nb * 8 + 2 * tg] = __floats2half2_rn(Oa[nb][2] * inv1, Oa[nb][3] * inv1);
    }
}

// ---------------- PDL launch helper ----------------
template <typename F, typename... Args>
static inline void launch_pdl(F kern, dim3 grid, dim3 block, size_t smem, Args... args) {
    cudaLaunchConfig_t cfg = {};
    cfg.gridDim = grid;
    cfg.blockDim = block;
    cfg.dynamicSmemBytes = smem;
    cfg.stream = 0;
    cudaLaunchAttribute attr[1];
    attr[0].id = cudaLaunchAttributeProgrammaticStreamSerialization;
    attr[0].val.programmaticStreamSerializationAllowed = 1;
    cfg.attrs = attr;
    cfg.numAttrs = 1;
    cudaLaunchKernelEx(&cfg, kern, args...);
}

// ---------------- launch ----------------
extern "C" void kernel_launch(void* const* d_in, const int* in_sizes, int n_in,
                              void* d_out, int out_size) {
    const float* x     = (const float*)d_in[0];
    const float* ln1w  = (const float*)d_in[1];
    const float* ln1b  = (const float*)d_in[2];
    const float* Wq    = (const float*)d_in[3];
    const float* bq    = (const float*)d_in[4];
    const float* Wk    = (const float*)d_in[5];
    const float* bk    = (const float*)d_in[6];
    const float* Wv    = (const float*)d_in[7];
    const float* bv    = (const float*)d_in[8];
    const float* Wproj = (const float*)d_in[9];
    const float* bproj = (const float*)d_in[10];
    const float* ln2w  = (const float*)d_in[11];
    const float* ln2b  = (const float*)d_in[12];
    const float* W1    = (const float*)d_in[13];
    const float* b1    = (const float*)d_in[14];
    const float* W2    = (const float*)d_in[15];
    const float* b2    = (const float*)d_in[16];
    float* out = (float*)d_out;

    __half *h, *qkvh, *o, *f1, *wqkvT, *wprojT, *w1T, *w2T;
    float *x1, *bqkv;
    cudaGetSymbolAddress((void**)&h, g_h);
    cudaGetSymbolAddress((void**)&qkvh, g_qkvh);
    cudaGetSymbolAddress((void**)&o, g_o);
    cudaGetSymbolAddress((void**)&x1, g_x1);
    cudaGetSymbolAddress((void**)&f1, g_f1);
    cudaGetSymbolAddress((void**)&wqkvT, g_WqkvT);
    cudaGetSymbolAddress((void**)&wprojT, g_WprojT);
    cudaGetSymbolAddress((void**)&w1T, g_W1T);
    cudaGetSymbolAddress((void**)&w2T, g_W2T);
    cudaGetSymbolAddress((void**)&bqkv, g_bqkv);

    cudaFuncSetAttribute(attn_mma, cudaFuncAttributeMaxDynamicSharedMemorySize, ATT_SMEM);
    cudaFuncSetAttribute(mma_gemm16<0, 1>, cudaFuncAttributeMaxDynamicSharedMemorySize, SMEM_TOTAL_G);
    cudaFuncSetAttribute(mma_gemm16<1, 0>, cudaFuncAttributeMaxDynamicSharedMemorySize, SMEM_TOTAL_G);
    cudaFuncSetAttribute(mma_gemm16<2, 1>, cudaFuncAttributeMaxDynamicSharedMemorySize, SMEM_TOTAL_G);

    // fused weight pack + LN1 (independent work, one kernel)
    pack_ln_kernel<<<PACK_BLOCKS + LN_BLOCKS, 256>>>(Wq, Wk, Wv, bq, bk, bv,
                                                     Wproj, W1, W2, x, ln1w, ln1b, h);
    // QKV GEMM (half out)  [PDL]
    launch_pdl(mma_gemm16<0, 1>, dim3(NQKV / 128, MM / 128), dim3(256), (size_t)SMEM_TOTAL_G,
               (const __half*)h, (const __half*)wqkvT, (const float*)bqkv,
               (const float*)nullptr, (void*)qkvh, MM, NQKV, CC);
    // flash attention  [PDL]
    launch_pdl(attn_mma, dim3(BB * HH * 2), dim3(256), (size_t)ATT_SMEM,
               (const __half*)qkvh, (__half*)o);
    // proj + residual (-> f32 x1)  [PDL]
    launch_pdl(mma_gemm16<1, 0>, dim3(CC / 128, MM / 128), dim3(256), (size_t)SMEM_TOTAL_G,
               (const __half*)o, (const __half*)wprojT, (const float*)bproj,
               (const float*)x, (void*)x1, MM, CC, CC);
    // LN2 (-> half)  [PDL]
    launch_pdl(ln_kernel, dim3(MM / 8), dim3(256), (size_t)0,
               (const float*)x1, (const float*)ln2w, (const float*)ln2b, (__half*)h);
    // FFN1 + GELU (-> half f1)  [PDL]
    launch_pdl(mma_gemm16<2, 1>, dim3(CF / 128, MM / 128), dim3(256), (size_t)SMEM_TOTAL_G,
               (const __half*)h, (const __half*)w1T, (const float*)b1,
               (const float*)nullptr, (void*)f1, MM, CF, CC);
    // FFN2 + residual (-> f32 out)  [PDL]
    launch_pdl(mma_gemm16<1, 0>, dim3(CC / 128, MM / 128), dim3(256), (size_t)SMEM_TOTAL_G,
               (const __half*)f1, (const __half*)w2T, (const float*)b2,
               (const float*)x1, (void*)out, MM, CC, CF);
}

// round 15
// speedup vs baseline: 1.0261x; 1.0261x over previous
#include <cuda_runtime.h>
#include <cuda_fp16.h>
#include <math.h>
#include <cstdint>

// Problem constants
#define BB 64
#define TT 256
#define CC 384
#define HH 6
#define HS 64
#define MM (BB * TT)          // 16384
#define NQKV (3 * CC)         // 1152
#define CF (4 * CC)           // 1536

// ---------------- scratch (static __device__, no allocs) ----------------
__device__ __half g_h[MM * CC];       // ln output (half, GEMM A input)
__device__ __half g_qkvh[MM * NQKV];  // packed Q|K|V (half)
__device__ __half g_o[MM * CC];       // attention output (half)
__device__ float  g_x1[MM * CC];      // first residual (f32)
__device__ __half g_f1[MM * CF];      // FFN hidden (half)
// transposed (N-major, K-contig) fp16 weights
__device__ __half g_WqkvT[NQKV * CC];
__device__ __half g_WprojT[CC * CC];
__device__ __half g_W1T[CF * CC];
__device__ __half g_W2T[CC * CF];
__device__ float  g_bqkv[NQKV];

__device__ __forceinline__ uint32_t smem_u32(const void* p) {
    uint32_t a;
    asm("{ .reg .u64 t; cvta.to.shared.u64 t, %1; cvt.u32.u64 %0, t; }" : "=r"(a) : "l"(p));
    return a;
}
__device__ __forceinline__ void grid_dep_sync() {
#if defined(__CUDA_ARCH__) && __CUDA_ARCH__ >= 900
    cudaGridDependencySynchronize();
#endif
}
__device__ __forceinline__ uint32_t h2u(__half2 v) {
    return *(uint32_t*)&v;
}

// ---------------- fused pack (all 4 weights + qkv bias) + LN1, one kernel ----------
#define N_QKVW (NQKV * CC)            // 442368
#define N_PROJ (CC * CC)              // 147456
#define N_W1   (CC * CF)              // 589824
#define N_W2   (CF * CC)              // 589824
#define OFF_PROJ N_QKVW
#define OFF_W1   (OFF_PROJ + N_PROJ)
#define OFF_W2   (OFF_W1 + N_W1)
#define N_PACK   (OFF_W2 + N_W2)      // 1769472
#define PACK_BLOCKS (N_PACK / 256)    // 6912
#define LN_BLOCKS (MM / 8)            // 2048

__device__ __forceinline__ void ln_row(const float* __restrict__ x,
                                       const float* __restrict__ w,
                                       const float* __restrict__ b,
                                       __half* __restrict__ y, int row, int lane) {
    const float4* xr = (const float4*)(x + (size_t)row * CC);
    float4 v0 = xr[lane], v1 = xr[lane + 32], v2 = xr[lane + 64];
    float s = v0.x + v0.y + v0.z + v0.w + v1.x + v1.y + v1.z + v1.w
            + v2.x + v2.y + v2.z + v2.w;
    float ss = v0.x * v0.x + v0.y * v0.y + v0.z * v0.z + v0.w * v0.w
             + v1.x * v1.x + v1.y * v1.y + v1.z * v1.z + v1.w * v1.w
             + v2.x * v2.x + v2.y * v2.y + v2.z * v2.z + v2.w * v2.w;
    #pragma unroll
    for (int o = 16; o > 0; o >>= 1) {
        s += __shfl_xor_sync(0xffffffffu, s, o);
        ss += __shfl_xor_sync(0xffffffffu, ss, o);
    }
    float mean = s * (1.0f / CC);
    float inv = rsqrtf(ss * (1.0f / CC) - mean * mean + 1e-5f);
    const float4* w4 = (const float4*)w;
    const float4* b4 = (const float4*)b;
    __half* yr = y + (size_t)row * CC;
    float4 vv[3] = {v0, v1, v2};
    #pragma unroll
    for (int j = 0; j < 3; j++) {
        float4 ww = w4[j * 32 + lane];
        float4 bb = b4[j * 32 + lane];
        float o0 = (vv[j].x - mean) * inv * ww.x + bb.x;
        float o1 = (vv[j].y - mean) * inv * ww.y + bb.y;
        float o2 = (vv[j].z - mean) * inv * ww.z + bb.z;
        float o3 = (vv[j].w - mean) * inv * ww.w + bb.w;
        uint2 pk;
        pk.x = h2u(__floats2half2_rn(o0, o1));
        pk.y = h2u(__floats2half2_rn(o2, o3));
        *(uint2*)&yr[j * 128 + 4 * lane] = pk;
    }
}

__global__ __launch_bounds__(256) void pack_ln_kernel(
        const float* __restrict__ Wq, const float* __restrict__ Wk,
        const float* __restrict__ Wv, const float* __restrict__ bq,
        const float* __restrict__ bk, const float* __restrict__ bv,
        const float* __restrict__ Wproj, const float* __restrict__ W1,
        const float* __restrict__ W2,
        const float* __restrict__ x, const float* __restrict__ ln1w,
        const float* __restrict__ ln1b, __half* __restrict__ hout) {
    int bid = blockIdx.x;
    if (bid < PACK_BLOCKS) {
        int i = bid * 256 + threadIdx.x;
        if (i < N_QKVW) {
            int n = i / CC, k = i % CC;
            int s2 = n / CC;
            int nn = n % CC;
            const float* src = (s2 == 0) ? Wq : (s2 == 1) ? Wk : Wv;
            g_WqkvT[i] = __float2half_rn(src[(nn / HS) * (CC * HS) + k * HS + (nn % HS)]);
        } else if (i < OFF_W1) {
            int j = i - OFF_PROJ;
            int n = j / CC, k = j % CC;
            g_WprojT[j] = __float2half_rn(Wproj[(size_t)k * CC + n]);
        } else if (i < OFF_W2) {
            int j = i - OFF_W1;
            int n = j / CC, k = j % CC;
            g_W1T[j] = __float2half_rn(W1[(size_t)k * CF + n]);
        } else if (i < N_PACK) {
            int j = i - OFF_W2;
            int n = j / CF, k = j % CF;
            g_W2T[j] = __float2half_rn(W2[(size_t)k * CC + n]);
        }
        if (i < NQKV) {
            int s2 = i / CC;
            int nn = i % CC;
            const float* sb = (s2 == 0) ? bq : (s2 == 1) ? bk : bv;
            g_bqkv[i] = sb[nn];
        }
    } else {
        int wid = threadIdx.x >> 5, lane = threadIdx.x & 31;
        int row = (bid - PACK_BLOCKS) * 8 + wid;
        ln_row(x, ln1w, ln1b, hout, row, lane);
    }
}

// ---------------- LayerNorm (LN2): one warp per row ----------------
__global__ __launch_bounds__(256) void ln_kernel(const float* __restrict__ x,
                                                 const float* __restrict__ w,
                                                 const float* __restrict__ b,
                                                 __half* __restrict__ y) {
    grid_dep_sync();
    int wid = threadIdx.x >> 5, lane = threadIdx.x & 31;
    int row = blockIdx.x * 8 + wid;
    ln_row(x, w, b, y, row, lane);
}

// ---------------- fp16 mma helpers ----------------
__device__ __forceinline__ void mma_f16(float* c, const uint32_t* a, const uint32_t* b) {
    asm volatile(
        "mma.sync.aligned.m16n8k16.row.col.f32.f16.f16.f32 "
        "{%0,%1,%2,%3}, {%4,%5,%6,%7}, {%8,%9}, {%0,%1,%2,%3};"
        : "+f"(c[0]), "+f"(c[1]), "+f"(c[2]), "+f"(c[3])
        : "r"(a[0]), "r"(a[1]), "r"(a[2]), "r"(a[3]), "r"(b[0]), "r"(b[1]));
}

__device__ __forceinline__ void cp16(uint32_t dst, const void* src) {
    asm volatile("cp.async.cg.shared.global [%0], [%1], 16;" :: "r"(dst), "l"(src));
}
__device__ __forceinline__ void ldsm4(uint32_t* r, uint32_t addr) {
    asm volatile("ldmatrix.sync.aligned.m8n8.x4.shared.b16 {%0,%1,%2,%3}, [%4];"
        : "=r"(r[0]), "=r"(r[1]), "=r"(r[2]), "=r"(r[3]) : "r"(addr));
}
__device__ __forceinline__ void ldsm4t(uint32_t* r, uint32_t addr) {
    asm volatile("ldmatrix.sync.aligned.m8n8.x4.trans.shared.b16 {%0,%1,%2,%3}, [%4];"
        : "=r"(r[0]), "=r"(r[1]), "=r"(r[2]), "=r"(r[3]) : "r"(addr));
}

// ---------------- fp16 mma.sync GEMM: 3-stage ring, 1 sync/chunk, 2 CTA/SM ---------
// C[M,N] = A[M,K] @ Bt[N,K]^T + bias ; MODE 0 bias, 1 bias+residual, 2 gelu(bias)
// CTA tile 128x128, 8 warps (2M x 4N), warp 64x32, K-chunk 64 halves (128B rows).
// Bias slice staged to smem before the mainloop (epilogue LDS instead of L2 LDG).
#define STG_A 16384                    // 128 rows * 128B
#define STG_T 32768                    // A + B per stage
#define SMEM_TOTAL_G (3 * STG_T)       // 98304 (3 stages)

template <int MODE, int OUTH>
__global__ __launch_bounds__(256, 2) void mma_gemm16(const __half* __restrict__ A,
                                                     const __half* __restrict__ Bt,
                                                     const float* __restrict__ bias,
                                                     const float* __restrict__ Rres,
                                                     void* __restrict__ Cout,
                                                     int M, int N, int K) {
    extern __shared__ __align__(16) char smem[];
    __shared__ float sBias[128];
    int tid = threadIdx.x;
    int lane = tid & 31, wid = tid >> 5;
    int warpM = wid & 1, warpN = wid >> 1;
    int g = lane >> 2, tg = lane & 3;
    int row0 = blockIdx.y * 128, col0 = blockIdx.x * 128;

    uint32_t sbase = smem_u32(smem);

    int cRow = tid >> 3;               // 0..31
    int cGrp = tid & 7;                // 16B group
    const __half* Ag = A + (size_t)(row0 + cRow) * K + cGrp * 8;
    const __half* Bg = Bt + (size_t)(col0 + cRow) * K + cGrp * 8;

    auto issue = [&](int c, int buf) {
        uint32_t dA = sbase + (uint32_t)buf * STG_T;
        uint32_t dB = dA + STG_A;
        #pragma unroll
        for (int pass = 0; pass < 4; pass++) {
            int row = cRow + pass * 32;
            uint32_t off = (uint32_t)row * 128 + (uint32_t)((cGrp ^ (row & 7)) << 4);
            cp16(dA + off, Ag + (size_t)(pass * 32) * K + c * 64);
            cp16(dB + off, Bg + (size_t)(pass * 32) * K + c * 64);
        }
        asm volatile("cp.async.commit_group;" ::: "memory");
    };

    int lr = lane & 7;
    int lh = (lane >> 3) & 1;
    uint32_t lk = (uint32_t)(lane >> 4);
    uint32_t aRowOff[4], aXor[4];
    #pragma unroll
    for (int mi = 0; mi < 4; mi++) {
        int row = warpM * 64 + mi * 16 + lr + lh * 8;
        aRowOff[mi] = (uint32_t)row * 128;
        aXor[mi] = (uint32_t)(row & 7);
    }
    uint32_t bRowOff[2], bXor[2];
    #pragma unroll
    for (int p = 0; p < 2; p++) {
        int row = warpN * 32 + p * 16 + lr + lh * 8;
        bRowOff[p] = (uint32_t)row * 128;
        bXor[p] = (uint32_t)(row & 7);
    }

    float acc[4][4][4];
    #pragma unroll
    for (int mi = 0; mi < 4; mi++)
        #pragma unroll
        for (int ni = 0; ni < 4; ni++)
            #pragma unroll
            for (int r = 0; r < 4; r++) acc[mi][ni][r] = 0.0f;

    grid_dep_sync();

    // stage bias slice (covered by mainloop barriers; nc >= 6 always)
    if (tid < 128) sBias[tid] = bias[col0 + tid];

    int nc = K / 64;
    issue(0, 0);
    if (nc > 1) issue(1, 1);
    if (nc > 2) issue(2, 2);

    for (int c = 0; c < nc; c++) {
        if (c + 1 < nc)
            asm volatile("cp.async.wait_group 1;" ::: "memory");
        else
            asm volatile("cp.async.wait_group 0;" ::: "memory");
        __syncthreads();
        if (c >= 1 && c + 2 < nc) issue(c + 2, (c + 2) % 3);

        uint32_t sA = sbase + (uint32_t)(c % 3) * STG_T;
        uint32_t sB = sA + STG_A;

        #pragma unroll
        for (int ks = 0; ks < 4; ks++) {
            uint32_t kg = (uint32_t)(ks * 2) + lk;
            uint32_t afr[4][4], breg[2][4];
            #pragma unroll
            for (int mi = 0; mi < 4; mi++)
                ldsm4(afr[mi], sA + aRowOff[mi] + ((kg ^ aXor[mi]) << 4));
            #pragma unroll
            for (int p = 0; p < 2; p++)
                ldsm4(breg[p], sB + bRowOff[p] + ((kg ^ bXor[p]) << 4));
            #pragma unroll
            for (int mi = 0; mi < 4; mi++) {
                #pragma unroll
                for (int p = 0; p < 2; p++) {
                    uint32_t b0[2] = {breg[p][0], breg[p][2]};
                    uint32_t b1[2] = {breg[p][1], breg[p][3]};
                    mma_f16(acc[mi][2 * p], afr[mi], b0);
                    mma_f16(acc[mi][2 * p + 1], afr[mi], b1);
                }
            }
        }
    }

    // epilogue
    #pragma unroll
    for (int mi = 0; mi < 4; mi++) {
        #pragma unroll
        for (int ni = 0; ni < 4; ni++) {
            int rA = row0 + warpM * 64 + mi * 16 + g;
            int cL = warpN * 32 + ni * 8 + tg * 2;
            int cA = col0 + cL;
            float b0 = sBias[cL], b1 = sBias[cL + 1];
            #pragma unroll
            for (int half = 0; half < 2; half++) {
                int r = rA + half * 8;
                float o0 = acc[mi][ni][half * 2 + 0] + b0;
                float o1 = acc[mi][ni][half * 2 + 1] + b1;
                size_t idx = (size_t)r * N + cA;
                if (MODE == 1) {
                    const float2 rr = *(const float2*)&Rres[idx];
                    o0 += rr.x; o1 += rr.y;
                }
                if (MODE == 2) {
                    o0 = 0.5f * o0 * (1.0f + erff(o0 * 0.70710678118654752f));
                    o1 = 0.5f * o1 * (1.0f + erff(o1 * 0.70710678118654752f));
                }
                if (OUTH) {
                    *(__half2*)((__half*)Cout + idx) = __floats2half2_rn(o0, o1);
                } else {
                    *(float2*)((float*)Cout + idx) = make_float2(o0, o1);
                }
            }
        }
    }
}

// ---------------- flash attention: balanced q-row pairing, ldmatrix, 2 CTA/SM ------
#define ATT_STG 32768                          // 256 rows * 128B
#define ATT_SMEM (2 * ATT_STG)                 // 65536

__global__ __launch_bounds__(256, 2) void attn_mma(const __half* __restrict__ qkv,
                                                   __half* __restrict__ o) {
    extern __shared__ __align__(16) char smh[];
    uint32_t sK = smem_u32(smh);
    uint32_t sV = sK + ATT_STG;
    int idx = blockIdx.x;
    int sel = idx & 1;
    int h = (idx >> 1) % HH;
    int b = idx / (2 * HH);
    size_t base = (size_t)b * TT * NQKV + (size_t)h * HS;
    int tid = threadIdx.x;
    int wid = tid >> 5, lane = tid & 31;
    int g = lane >> 2, tg = lane & 3;

    int glo = sel ? 1 : 0;
    int ghi = sel ? 2 : 3;
    int nkeys = (ghi + 1) * 64;            // 256 or 192
    int grp = (wid < 4) ? glo : ghi;
    int qbase = grp * 64 + (wid & 3) * 16;

    grid_dep_sync();

    // cp.async fill of K and V (swizzled rows)
    {
        int cRow = tid >> 3, cGrp = tid & 7;
        const __half* Kg = qkv + base + CC + (size_t)cRow * NQKV + cGrp * 8;
        const __half* Vg = qkv + base + 2 * CC + (size_t)cRow * NQKV + cGrp * 8;
        int np = nkeys / 32;
        for (int pass = 0; pass < np; pass++) {
            int row = cRow + pass * 32;
            uint32_t off = (uint32_t)row * 128 + (uint32_t)((cGrp ^ (row & 7)) << 4);
            cp16(sK + off, Kg + (size_t)(pass * 32) * NQKV);
            cp16(sV + off, Vg + (size_t)(pass * 32) * NQKV);
        }
        asm volatile("cp.async.commit_group;" ::: "memory");
    }

    // Q fragments from gmem (overlaps with cp.async)
    uint32_t qf[4][4];
    const __half* qp = &qkv[base + (size_t)qbase * NQKV];
    #pragma unroll
    for (int ks = 0; ks < 4; ks++) {
        int d0 = ks * 16;
        qf[ks][0] = *(const uint32_t*)&qp[(size_t)g * NQKV + d0 + 2 * tg];
        qf[ks][1] = *(const uint32_t*)&qp[(size_t)(g + 8) * NQKV + d0 + 2 * tg];
        qf[ks][2] = *(const uint32_t*)&qp[(size_t)g * NQKV + d0 + 8 + 2 * tg];
        qf[ks][3] = *(const uint32_t*)&qp[(size_t)(g + 8) * NQKV + d0 + 8 + 2 * tg];
    }

    int lr = lane & 7;
    int lh = (lane >> 3) & 1;
    uint32_t lk = (uint32_t)(lane >> 4);
    int kRowLoc = lr + lh * 8;
    int vRowLoc = lr + lh * 8;

    asm volatile("cp.async.wait_group 0;" ::: "memory");
    __syncthreads();

    float Oa[8][4];
    #pragma unroll
    for (int nb = 0; nb < 8; nb++)
        #pragma unroll
        for (int j = 0; j < 4; j++) Oa[nb][j] = 0.0f;
    float m0 = -1e30f, m1 = -1e30f, l0 = 0.0f, l1 = 0.0f;

    int ktmax = (qbase + 15) >> 6;
    for (int kt = 0; kt <= ktmax; kt++) {
        float S[8][4];
        #pragma unroll
        for (int nb = 0; nb < 8; nb++)
            #pragma unroll
            for (int j = 0; j < 4; j++) S[nb][j] = 0.0f;

        // S = Q @ K^T
        #pragma unroll
        for (int ks = 0; ks < 4; ks++) {
            uint32_t kg = (uint32_t)(ks * 2) + lk;
            #pragma unroll
            for (int p = 0; p < 4; p++) {
                int row = kt * 64 + p * 16 + kRowLoc;
                uint32_t br[4];
                ldsm4(br, sK + (uint32_t)row * 128 + ((kg ^ (uint32_t)(row & 7)) << 4));
                uint32_t b0[2] = {br[0], br[2]};
                uint32_t b1[2] = {br[1], br[3]};
                mma_f16(S[2 * p], qf[ks], b0);
                mma_f16(S[2 * p + 1], qf[ks], b1);
            }
        }
        #pragma unroll
        for (int nb = 0; nb < 8; nb++)
            #pragma unroll
            for (int j = 0; j < 4; j++) S[nb][j] *= 0.125f;
        if (kt == ktmax) {
            int r0 = qbase + g, r1 = r0 + 8;
            #pragma unroll
            for (int nb = 0; nb < 8; nb++) {
                int col = kt * 64 + nb * 8 + 2 * tg;
                if (col > r0)     S[nb][0] = -1e30f;
                if (col + 1 > r0) S[nb][1] = -1e30f;
                if (col > r1)     S[nb][2] = -1e30f;
                if (col + 1 > r1) S[nb][3] = -1e30f;
            }
        }
        float tm0 = -1e30f, tm1 = -1e30f;
        #pragma unroll
        for (int nb = 0; nb < 8; nb++) {
            tm0 = fmaxf(tm0, fmaxf(S[nb][0], S[nb][1]));
            tm1 = fmaxf(tm1, fmaxf(S[nb][2], S[nb][3]));
        }
        tm0 = fmaxf(tm0, __shfl_xor_sync(0xffffffffu, tm0, 1));
        tm0 = fmaxf(tm0, __shfl_xor_sync(0xffffffffu, tm0, 2));
        tm1 = fmaxf(tm1, __shfl_xor_sync(0xffffffffu, tm1, 1));
        tm1 = fmaxf(tm1, __shfl_xor_sync(0xffffffffu, tm1, 2));
        float mn0 = fmaxf(m0, tm0), mn1 = fmaxf(m1, tm1);
        float sc0 = __expf(m0 - mn0), sc1 = __expf(m1 - mn1);
        float ts0 = 0.0f, ts1 = 0.0f;
        #pragma unroll
        for (int nb = 0; nb < 8; nb++) {
            S[nb][0] = __expf(S[nb][0] - mn0);
            S[nb][1] = __expf(S[nb][1] - mn0);
            S[nb][2] = __expf(S[nb][2] - mn1);
            S[nb][3] = __expf(S[nb][3] - mn1);
            ts0 += S[nb][0] + S[nb][1];
            ts1 += S[nb][2] + S[nb][3];
        }
        ts0 += __shfl_xor_sync(0xffffffffu, ts0, 1);
        ts0 += __shfl_xor_sync(0xffffffffu, ts0, 2);
        ts1 += __shfl_xor_sync(0xffffffffu, ts1, 1);
        ts1 += __shfl_xor_sync(0xffffffffu, ts1, 2);
        l0 = l0 * sc0 + ts0;
        l1 = l1 * sc1 + ts1;
        m0 = mn0; m1 = mn1;
        #pragma unroll
        for (int nb = 0; nb < 8; nb++) {
            Oa[nb][0] *= sc0; Oa[nb][1] *= sc0;
            Oa[nb][2] *= sc1; Oa[nb][3] *= sc1;
        }
        // O += P @ V (ldmatrix.trans on V rows)
        #pragma unroll
        for (int ks = 0; ks < 4; ks++) {
            uint32_t ap[4];
            ap[0] = h2u(__floats2half2_rn(S[2 * ks][0], S[2 * ks][1]));
            ap[1] = h2u(__floats2half2_rn(S[2 * ks][2], S[2 * ks][3]));
            ap[2] = h2u(__floats2half2_rn(S[2 * ks + 1][0], S[2 * ks + 1][1]));
            ap[3] = h2u(__floats2half2_rn(S[2 * ks + 1][2], S[2 * ks + 1][3]));
            int krow = kt * 64 + ks * 16 + vRowLoc;
            uint32_t rbase = sV + (uint32_t)krow * 128;
            uint32_t rx = (uint32_t)(krow & 7);
            #pragma unroll
            for (int dp = 0; dp < 4; dp++) {
                uint32_t cg = (uint32_t)(dp * 2) + lk;
                uint32_t vr[4];
                ldsm4t(vr, rbase + ((cg ^ rx) << 4));
                uint32_t b0[2] = {vr[0], vr[1]};
                uint32_t b1[2] = {vr[2], vr[3]};
                mma_f16(Oa[2 * dp], ap, b0);
                mma_f16(Oa[2 * dp + 1], ap, b1);
            }
        }
    }

    float inv0 = 1.0f / l0, inv1 = 1.0f / l1;
    __half* op = o + ((size_t)(b * TT + qbase + g) * CC + h * HS);
    __half* op1 = op + 8 * CC;
    #pragma unroll
    for (int nb = 0; nb < 8; nb++) {
        *(__half2*)&op[nb * 8 + 2 * tg]  = __floats2half2_rn(Oa[nb][0] * inv0, Oa[nb][1] * inv0);
        *(__half2*)&op1[nb * 8 + 2 * tg] = __floats2half2_rn(Oa[nb][2] * inv1, Oa[nb][3] * inv1);
    }
}

// ---------------- PDL launch helper ----------------
template <typename F, typename... Args>
static inline void launch_pdl(F kern, dim3 grid, dim3 block, size_t smem, Args... args) {
    cudaLaunchConfig_t cfg = {};
    cfg.gridDim = grid;
    cfg.blockDim = block;
    cfg.dynamicSmemBytes = smem;
    cfg.stream = 0;
    cudaLaunchAttribute attr[1];
    attr[0].id = cudaLaunchAttributeProgrammaticStreamSerialization;
    attr[0].val.programmaticStreamSerializationAllowed = 1;
    cfg.attrs = attr;
    cfg.numAttrs = 1;
    cudaLaunchKernelEx(&cfg, kern, args...);
}

// ---------------- launch ----------------
extern "C" void kernel_launch(void* const* d_in, const int* in_sizes, int n_in,
                              void* d_out, int out_size) {
    const float* x     = (const float*)d_in[0];
    const float* ln1w  = (const float*)d_in[1];
    const float* ln1b  = (const float*)d_in[2];
    const float* Wq    = (const float*)d_in[3];
    const float* bq    = (const float*)d_in[4];
    const float* Wk    = (const float*)d_in[5];
    const float* bk    = (const float*)d_in[6];
    const float* Wv    = (const float*)d_in[7];
    const float* bv    = (const float*)d_in[8];
    const float* Wproj = (const float*)d_in[9];
    const float* bproj = (const float*)d_in[10];
    const float* ln2w  = (const float*)d_in[11];
    const float* ln2b  = (const float*)d_in[12];
    const float* W1    = (const float*)d_in[13];
    const float* b1    = (const float*)d_in[14];
    const float* W2    = (const float*)d_in[15];
    const float* b2    = (const float*)d_in[16];
    float* out = (float*)d_out;

    __half *h, *qkvh, *o, *f1, *wqkvT, *wprojT, *w1T, *w2T;
    float *x1, *bqkv;
    cudaGetSymbolAddress((void**)&h, g_h);
    cudaGetSymbolAddress((void**)&qkvh, g_qkvh);
    cudaGetSymbolAddress((void**)&o, g_o);
    cudaGetSymbolAddress((void**)&x1, g_x1);
    cudaGetSymbolAddress((void**)&f1, g_f1);
    cudaGetSymbolAddress((void**)&wqkvT, g_WqkvT);
    cudaGetSymbolAddress((void**)&wprojT, g_WprojT);
    cudaGetSymbolAddress((void**)&w1T, g_W1T);
    cudaGetSymbolAddress((void**)&w2T, g_W2T);
    cudaGetSymbolAddress((void**)&bqkv, g_bqkv);

    cudaFuncSetAttribute(attn_mma, cudaFuncAttributeMaxDynamicSharedMemorySize, ATT_SMEM);
    cudaFuncSetAttribute(mma_gemm16<0, 1>, cudaFuncAttributeMaxDynamicSharedMemorySize, SMEM_TOTAL_G);
    cudaFuncSetAttribute(mma_gemm16<1, 0>, cudaFuncAttributeMaxDynamicSharedMemorySize, SMEM_TOTAL_G);
    cudaFuncSetAttribute(mma_gemm16<2, 1>, cudaFuncAttributeMaxDynamicSharedMemorySize, SMEM_TOTAL_G);

    // fused weight pack + LN1 (independent work, one kernel)
    pack_ln_kernel<<<PACK_BLOCKS + LN_BLOCKS, 256>>>(Wq, Wk, Wv, bq, bk, bv,
                                                     Wproj, W1, W2, x, ln1w, ln1b, h);
    // QKV GEMM (half out)  [PDL]
    launch_pdl(mma_gemm16<0, 1>, dim3(NQKV / 128, MM / 128), dim3(256), (size_t)SMEM_TOTAL_G,
               (const __half*)h, (const __half*)wqkvT, (const float*)bqkv,
               (const float*)nullptr, (void*)qkvh, MM, NQKV, CC);
    // flash attention  [PDL]
    launch_pdl(attn_mma, dim3(BB * HH * 2), dim3(256), (size_t)ATT_SMEM,
               (const __half*)qkvh, (__half*)o);
    // proj + residual (-> f32 x1)  [PDL]
    launch_pdl(mma_gemm16<1, 0>, dim3(CC / 128, MM / 128), dim3(256), (size_t)SMEM_TOTAL_G,
               (const __half*)o, (const __half*)wprojT, (const float*)bproj,
               (const float*)x, (void*)x1, MM, CC, CC);
    // LN2 (-> half)  [PDL]
    launch_pdl(ln_kernel, dim3(MM / 8), dim3(256), (size_t)0,
               (const float*)x1, (const float*)ln2w, (const float*)ln2b, (__half*)h);
    // FFN1 + GELU (-> half f1)  [PDL]
    launch_pdl(mma_gemm16<2, 1>, dim3(CF / 128, MM / 128), dim3(256), (size_t)SMEM_TOTAL_G,
               (const __half*)h, (const __half*)w1T, (const float*)b1,
               (const float*)nullptr, (void*)f1, MM, CF, CC);
    // FFN2 + residual (-> f32 out)  [PDL]
    launch_pdl(mma_gemm16<1, 0>, dim3(CC / 128, MM / 128), dim3(256), (size_t)SMEM_TOTAL_G,
               (const __half*)f1, (const __half*)w2T, (const float*)b2,
               (const float*)x1, (void*)out, MM, CC, CF);
}

// round 16
// speedup vs baseline: 1.0321x; 1.0058x over previous
#include <cuda_runtime.h>
#include <cuda_fp16.h>
#include <math.h>
#include <cstdint>

// Problem constants
#define BB 64
#define TT 256
#define CC 384
#define HH 6
#define HS 64
#define MM (BB * TT)          // 16384
#define NQKV (3 * CC)         // 1152
#define CF (4 * CC)           // 1536

// ---------------- scratch (static __device__, no allocs) ----------------
__device__ __half g_h[MM * CC];       // ln output (half, GEMM A input)
__device__ __half g_qkvh[MM * NQKV];  // packed Q|K|V (half)
__device__ __half g_o[MM * CC];       // attention output (half)
__device__ float  g_x1[MM * CC];      // first residual (f32)
__device__ __half g_f1[MM * CF];      // FFN hidden (half)
// transposed (N-major, K-contig) fp16 weights
__device__ __half g_WqkvT[NQKV * CC];
__device__ __half g_WprojT[CC * CC];
__device__ __half g_W1T[CF * CC];
__device__ __half g_W2T[CC * CF];
__device__ float  g_bqkv[NQKV];

__device__ __forceinline__ uint32_t smem_u32(const void* p) {
    uint32_t a;
    asm("{ .reg .u64 t; cvta.to.shared.u64 t, %1; cvt.u32.u64 %0, t; }" : "=r"(a) : "l"(p));
    return a;
}
__device__ __forceinline__ void grid_dep_sync() {
#if defined(__CUDA_ARCH__) && __CUDA_ARCH__ >= 900
    cudaGridDependencySynchronize();
#endif
}
__device__ __forceinline__ uint32_t h2u(__half2 v) {
    return *(uint32_t*)&v;
}

// ---------------- fused pack (all 4 weights + qkv bias) + LN1, one kernel ----------
#define N_QKVW (NQKV * CC)            // 442368
#define N_PROJ (CC * CC)              // 147456
#define N_W1   (CC * CF)              // 589824
#define N_W2   (CF * CC)              // 589824
#define OFF_PROJ N_QKVW
#define OFF_W1   (OFF_PROJ + N_PROJ)
#define OFF_W2   (OFF_W1 + N_W1)
#define N_PACK   (OFF_W2 + N_W2)      // 1769472
#define PACK_BLOCKS (N_PACK / 256)    // 6912
#define LN_BLOCKS (MM / 8)            // 2048

__device__ __forceinline__ void ln_row(const float* __restrict__ x,
                                       const float* __restrict__ w,
                                       const float* __restrict__ b,
                                       __half* __restrict__ y, int row, int lane) {
    const float4* xr = (const float4*)(x + (size_t)row * CC);
    float4 v0 = xr[lane], v1 = xr[lane + 32], v2 = xr[lane + 64];
    float s = v0.x + v0.y + v0.z + v0.w + v1.x + v1.y + v1.z + v1.w
            + v2.x + v2.y + v2.z + v2.w;
    float ss = v0.x * v0.x + v0.y * v0.y + v0.z * v0.z + v0.w * v0.w
             + v1.x * v1.x + v1.y * v1.y + v1.z * v1.z + v1.w * v1.w
             + v2.x * v2.x + v2.y * v2.y + v2.z * v2.z + v2.w * v2.w;
    #pragma unroll
    for (int o = 16; o > 0; o >>= 1) {
        s += __shfl_xor_sync(0xffffffffu, s, o);
        ss += __shfl_xor_sync(0xffffffffu, ss, o);
    }
    float mean = s * (1.0f / CC);
    float inv = rsqrtf(ss * (1.0f / CC) - mean * mean + 1e-5f);
    const float4* w4 = (const float4*)w;
    const float4* b4 = (const float4*)b;
    __half* yr = y + (size_t)row * CC;
    float4 vv[3] = {v0, v1, v2};
    #pragma unroll
    for (int j = 0; j < 3; j++) {
        float4 ww = w4[j * 32 + lane];
        float4 bb = b4[j * 32 + lane];
        float o0 = (vv[j].x - mean) * inv * ww.x + bb.x;
        float o1 = (vv[j].y - mean) * inv * ww.y + bb.y;
        float o2 = (vv[j].z - mean) * inv * ww.z + bb.z;
        float o3 = (vv[j].w - mean) * inv * ww.w + bb.w;
        uint2 pk;
        pk.x = h2u(__floats2half2_rn(o0, o1));
        pk.y = h2u(__floats2half2_rn(o2, o3));
        *(uint2*)&yr[j * 128 + 4 * lane] = pk;
    }
}

__global__ __launch_bounds__(256) void pack_ln_kernel(
        const float* __restrict__ Wq, const float* __restrict__ Wk,
        const float* __restrict__ Wv, const float* __restrict__ bq,
        const float* __restrict__ bk, const float* __restrict__ bv,
        const float* __restrict__ Wproj, const float* __restrict__ W1,
        const float* __restrict__ W2,
        const float* __restrict__ x, const float* __restrict__ ln1w,
        const float* __restrict__ ln1b, __half* __restrict__ hout) {
    int bid = blockIdx.x;
    if (bid < PACK_BLOCKS) {
        int i = bid * 256 + threadIdx.x;
        if (i < N_QKVW) {
            int n = i / CC, k = i % CC;
            int s2 = n / CC;
            int nn = n % CC;
            const float* src = (s2 == 0) ? Wq : (s2 == 1) ? Wk : Wv;
            g_WqkvT[i] = __float2half_rn(src[(nn / HS) * (CC * HS) + k * HS + (nn % HS)]);
        } else if (i < OFF_W1) {
            int j = i - OFF_PROJ;
            int n = j / CC, k = j % CC;
            g_WprojT[j] = __float2half_rn(Wproj[(size_t)k * CC + n]);
        } else if (i < OFF_W2) {
            int j = i - OFF_W1;
            int n = j / CC, k = j % CC;
            g_W1T[j] = __float2half_rn(W1[(size_t)k * CF + n]);
        } else if (i < N_PACK) {
            int j = i - OFF_W2;
            int n = j / CF, k = j % CF;
            g_W2T[j] = __float2half_rn(W2[(size_t)k * CC + n]);
        }
        if (i < NQKV) {
            int s2 = i / CC;
            int nn = i % CC;
            const float* sb = (s2 == 0) ? bq : (s2 == 1) ? bk : bv;
            g_bqkv[i] = sb[nn];
        }
    } else {
        int wid = threadIdx.x >> 5, lane = threadIdx.x & 31;
        int row = (bid - PACK_BLOCKS) * 8 + wid;
        ln_row(x, ln1w, ln1b, hout, row, lane);
    }
}

// ---------------- LayerNorm (LN2): one warp per row ----------------
__global__ __launch_bounds__(256) void ln_kernel(const float* __restrict__ x,
                                                 const float* __restrict__ w,
                                                 const float* __restrict__ b,
                                                 __half* __restrict__ y) {
    grid_dep_sync();
    int wid = threadIdx.x >> 5, lane = threadIdx.x & 31;
    int row = blockIdx.x * 8 + wid;
    ln_row(x, w, b, y, row, lane);
}

// ---------------- fp16 mma helpers ----------------
__device__ __forceinline__ void mma_f16(float* c, const uint32_t* a, const uint32_t* b) {
    asm volatile(
        "mma.sync.aligned.m16n8k16.row.col.f32.f16.f16.f32 "
        "{%0,%1,%2,%3}, {%4,%5,%6,%7}, {%8,%9}, {%0,%1,%2,%3};"
        : "+f"(c[0]), "+f"(c[1]), "+f"(c[2]), "+f"(c[3])
        : "r"(a[0]), "r"(a[1]), "r"(a[2]), "r"(a[3]), "r"(b[0]), "r"(b[1]));
}

__device__ __forceinline__ void cp16(uint32_t dst, const void* src) {
    asm volatile("cp.async.cg.shared.global [%0], [%1], 16;" :: "r"(dst), "l"(src));
}
__device__ __forceinline__ void ldsm4(uint32_t* r, uint32_t addr) {
    asm volatile("ldmatrix.sync.aligned.m8n8.x4.shared.b16 {%0,%1,%2,%3}, [%4];"
        : "=r"(r[0]), "=r"(r[1]), "=r"(r[2]), "=r"(r[3]) : "r"(addr));
}
__device__ __forceinline__ void ldsm4t(uint32_t* r, uint32_t addr) {
    asm volatile("ldmatrix.sync.aligned.m8n8.x4.trans.shared.b16 {%0,%1,%2,%3}, [%4];"
        : "=r"(r[0]), "=r"(r[1]), "=r"(r[2]), "=r"(r[3]) : "r"(addr));
}

// ---------------- fp16 mma.sync GEMM: 3-stage ring, 1 sync/chunk, 2 CTA/SM ---------
// C[M,N] = A[M,K] @ Bt[N,K]^T + bias ; MODE 0 bias, 1 bias+residual, 2 gelu(bias)
// CTA tile 128x128, 8 warps (2M x 4N), warp 64x32, K-chunk 64 halves (128B rows).
#define STG_A 16384                    // 128 rows * 128B
#define STG_T 32768                    // A + B per stage
#define SMEM_TOTAL_G (3 * STG_T)       // 98304 (3 stages)

template <int MODE, int OUTH>
__global__ __launch_bounds__(256, 2) void mma_gemm16(const __half* __restrict__ A,
                                                     const __half* __restrict__ Bt,
                                                     const float* __restrict__ bias,
                                                     const float* __restrict__ Rres,
                                                     void* __restrict__ Cout,
                                                     int M, int N, int K) {
    extern __shared__ __align__(16) char smem[];
    int tid = threadIdx.x;
    int lane = tid & 31, wid = tid >> 5;
    int warpM = wid & 1, warpN = wid >> 1;
    int g = lane >> 2, tg = lane & 3;
    int row0 = blockIdx.y * 128, col0 = blockIdx.x * 128;

    uint32_t sbase = smem_u32(smem);

    int cRow = tid >> 3;               // 0..31
    int cGrp = tid & 7;                // 16B group
    const __half* Ag = A + (size_t)(row0 + cRow) * K + cGrp * 8;
    const __half* Bg = Bt + (size_t)(col0 + cRow) * K + cGrp * 8;

    auto issue = [&](int c, int buf) {
        uint32_t dA = sbase + (uint32_t)buf * STG_T;
        uint32_t dB = dA + STG_A;
        #pragma unroll
        for (int pass = 0; pass < 4; pass++) {
            int row = cRow + pass * 32;
            uint32_t off = (uint32_t)row * 128 + (uint32_t)((cGrp ^ (row & 7)) << 4);
            cp16(dA + off, Ag + (size_t)(pass * 32) * K + c * 64);
            cp16(dB + off, Bg + (size_t)(pass * 32) * K + c * 64);
        }
        asm volatile("cp.async.commit_group;" ::: "memory");
    };

    int lr = lane & 7;
    int lh = (lane >> 3) & 1;
    uint32_t lk = (uint32_t)(lane >> 4);
    uint32_t aRowOff[4], aXor[4];
    #pragma unroll
    for (int mi = 0; mi < 4; mi++) {
        int row = warpM * 64 + mi * 16 + lr + lh * 8;
        aRowOff[mi] = (uint32_t)row * 128;
        aXor[mi] = (uint32_t)(row & 7);
    }
    uint32_t bRowOff[2], bXor[2];
    #pragma unroll
    for (int p = 0; p < 2; p++) {
        int row = warpN * 32 + p * 16 + lr + lh * 8;
        bRowOff[p] = (uint32_t)row * 128;
        bXor[p] = (uint32_t)(row & 7);
    }

    float acc[4][4][4];
    #pragma unroll
    for (int mi = 0; mi < 4; mi++)
        #pragma unroll
        for (int ni = 0; ni < 4; ni++)
            #pragma unroll
            for (int r = 0; r < 4; r++) acc[mi][ni][r] = 0.0f;

    grid_dep_sync();

    int nc = K / 64;
    issue(0, 0);
    if (nc > 1) issue(1, 1);
    if (nc > 2) issue(2, 2);

    for (int c = 0; c < nc; c++) {
        if (c + 1 < nc)
            asm volatile("cp.async.wait_group 1;" ::: "memory");
        else
            asm volatile("cp.async.wait_group 0;" ::: "memory");
        __syncthreads();
        if (c >= 1 && c + 2 < nc) issue(c + 2, (c + 2) % 3);

        uint32_t sA = sbase + (uint32_t)(c % 3) * STG_T;
        uint32_t sB = sA + STG_A;

        #pragma unroll
        for (int ks = 0; ks < 4; ks++) {
            uint32_t kg = (uint32_t)(ks * 2) + lk;
            uint32_t afr[4][4], breg[2][4];
            #pragma unroll
            for (int mi = 0; mi < 4; mi++)
                ldsm4(afr[mi], sA + aRowOff[mi] + ((kg ^ aXor[mi]) << 4));
            #pragma unroll
            for (int p = 0; p < 2; p++)
                ldsm4(breg[p], sB + bRowOff[p] + ((kg ^ bXor[p]) << 4));
            #pragma unroll
            for (int mi = 0; mi < 4; mi++) {
                #pragma unroll
                for (int p = 0; p < 2; p++) {
                    uint32_t b0[2] = {breg[p][0], breg[p][2]};
                    uint32_t b1[2] = {breg[p][1], breg[p][3]};
                    mma_f16(acc[mi][2 * p], afr[mi], b0);
                    mma_f16(acc[mi][2 * p + 1], afr[mi], b1);
                }
            }
        }
    }

    // epilogue
    #pragma unroll
    for (int mi = 0; mi < 4; mi++) {
        #pragma unroll
        for (int ni = 0; ni < 4; ni++) {
            int rA = row0 + warpM * 64 + mi * 16 + g;
            int cA = col0 + warpN * 32 + ni * 8 + tg * 2;
            float b0 = bias[cA], b1 = bias[cA + 1];
            #pragma unroll
            for (int half = 0; half < 2; half++) {
                int r = rA + half * 8;
                float o0 = acc[mi][ni][half * 2 + 0] + b0;
                float o1 = acc[mi][ni][half * 2 + 1] + b1;
                size_t idx = (size_t)r * N + cA;
                if (MODE == 1) {
                    const float2 rr = *(const float2*)&Rres[idx];
                    o0 += rr.x; o1 += rr.y;
                }
                if (MODE == 2) {
                    o0 = 0.5f * o0 * (1.0f + erff(o0 * 0.70710678118654752f));
                    o1 = 0.5f * o1 * (1.0f + erff(o1 * 0.70710678118654752f));
                }
                if (OUTH) {
                    *(__half2*)((__half*)Cout + idx) = __floats2half2_rn(o0, o1);
                } else {
                    *(float2*)((float*)Cout + idx) = make_float2(o0, o1);
                }
            }
        }
    }
}

// ---------------- flash attention: balanced q-row pairing, ldmatrix, 2 CTA/SM ------
#define ATT_STG 32768                          // 256 rows * 128B
#define ATT_SMEM (2 * ATT_STG)                 // 65536

__global__ __launch_bounds__(256, 2) void attn_mma(const __half* __restrict__ qkv,
                                                   __half* __restrict__ o) {
    extern __shared__ __align__(16) char smh[];
    uint32_t sK = smem_u32(smh);
    uint32_t sV = sK + ATT_STG;
    int idx = blockIdx.x;
    int sel = idx & 1;
    int h = (idx >> 1) % HH;
    int b = idx / (2 * HH);
    size_t base = (size_t)b * TT * NQKV + (size_t)h * HS;
    int tid = threadIdx.x;
    int wid = tid >> 5, lane = tid & 31;
    int g = lane >> 2, tg = lane & 3;

    int glo = sel ? 1 : 0;
    int ghi = sel ? 2 : 3;
    int nkeys = (ghi + 1) * 64;            // 256 or 192
    int grp = (wid < 4) ? glo : ghi;
    int qbase = grp * 64 + (wid & 3) * 16;

    grid_dep_sync();

    // cp.async fill of K and V (swizzled rows)
    {
        int cRow = tid >> 3, cGrp = tid & 7;
        const __half* Kg = qkv + base + CC + (size_t)cRow * NQKV + cGrp * 8;
        const __half* Vg = qkv + base + 2 * CC + (size_t)cRow * NQKV + cGrp * 8;
        int np = nkeys / 32;
        for (int pass = 0; pass < np; pass++) {
            int row = cRow + pass * 32;
            uint32_t off = (uint32_t)row * 128 + (uint32_t)((cGrp ^ (row & 7)) << 4);
            cp16(sK + off, Kg + (size_t)(pass * 32) * NQKV);
            cp16(sV + off, Vg + (size_t)(pass * 32) * NQKV);
        }
        asm volatile("cp.async.commit_group;" ::: "memory");
    }

    // Q fragments from gmem (overlaps with cp.async)
    uint32_t qf[4][4];
    const __half* qp = &qkv[base + (size_t)qbase * NQKV];
    #pragma unroll
    for (int ks = 0; ks < 4; ks++) {
        int d0 = ks * 16;
        qf[ks][0] = *(const uint32_t*)&qp[(size_t)g * NQKV + d0 + 2 * tg];
        qf[ks][1] = *(const uint32_t*)&qp[(size_t)(g + 8) * NQKV + d0 + 2 * tg];
        qf[ks][2] = *(const uint32_t*)&qp[(size_t)g * NQKV + d0 + 8 + 2 * tg];
        qf[ks][3] = *(const uint32_t*)&qp[(size_t)(g + 8) * NQKV + d0 + 8 + 2 * tg];
    }

    int lr = lane & 7;
    int lh = (lane >> 3) & 1;
    uint32_t lk = (uint32_t)(lane >> 4);
    int kRowLoc = lr + lh * 8;
    int vRowLoc = lr + lh * 8;

    asm volatile("cp.async.wait_group 0;" ::: "memory");
    __syncthreads();

    float Oa[8][4];
    #pragma unroll
    for (int nb = 0; nb < 8; nb++)
        #pragma unroll
        for (int j = 0; j < 4; j++) Oa[nb][j] = 0.0f;
    float m0 = -1e30f, m1 = -1e30f, l0 = 0.0f, l1 = 0.0f;

    int ktmax = (qbase + 15) >> 6;
    for (int kt = 0; kt <= ktmax; kt++) {
        float S[8][4];
        #pragma unroll
        for (int nb = 0; nb < 8; nb++)
            #pragma unroll
            for (int j = 0; j < 4; j++) S[nb][j] = 0.0f;

        // S = Q @ K^T
        #pragma unroll
        for (int ks = 0; ks < 4; ks++) {
            uint32_t kg = (uint32_t)(ks * 2) + lk;
            #pragma unroll
            for (int p = 0; p < 4; p++) {
                int row = kt * 64 + p * 16 + kRowLoc;
                uint32_t br[4];
                ldsm4(br, sK + (uint32_t)row * 128 + ((kg ^ (uint32_t)(row & 7)) << 4));
                uint32_t b0[2] = {br[0], br[2]};
                uint32_t b1[2] = {br[1], br[3]};
                mma_f16(S[2 * p], qf[ks], b0);
                mma_f16(S[2 * p + 1], qf[ks], b1);
            }
        }
        #pragma unroll
        for (int nb = 0; nb < 8; nb++)
            #pragma unroll
            for (int j = 0; j < 4; j++) S[nb][j] *= 0.125f;
        if (kt == ktmax) {
            int r0 = qbase + g, r1 = r0 + 8;
            #pragma unroll
            for (int nb = 0; nb < 8; nb++) {
                int col = kt * 64 + nb * 8 + 2 * tg;
                if (col > r0)     S[nb][0] = -1e30f;
                if (col + 1 > r0) S[nb][1] = -1e30f;
                if (col > r1)     S[nb][2] = -1e30f;
                if (col + 1 > r1) S[nb][3] = -1e30f;
            }
        }
        float tm0 = -1e30f, tm1 = -1e30f;
        #pragma unroll
        for (int nb = 0; nb < 8; nb++) {
            tm0 = fmaxf(tm0, fmaxf(S[nb][0], S[nb][1]));
            tm1 = fmaxf(tm1, fmaxf(S[nb][2], S[nb][3]));
        }
        tm0 = fmaxf(tm0, __shfl_xor_sync(0xffffffffu, tm0, 1));
        tm0 = fmaxf(tm0, __shfl_xor_sync(0xffffffffu, tm0, 2));
        tm1 = fmaxf(tm1, __shfl_xor_sync(0xffffffffu, tm1, 1));
        tm1 = fmaxf(tm1, __shfl_xor_sync(0xffffffffu, tm1, 2));
        float mn0 = fmaxf(m0, tm0), mn1 = fmaxf(m1, tm1);
        float sc0 = __expf(m0 - mn0), sc1 = __expf(m1 - mn1);
        float ts0 = 0.0f, ts1 = 0.0f;
        #pragma unroll
        for (int nb = 0; nb < 8; nb++) {
            S[nb][0] = __expf(S[nb][0] - mn0);
            S[nb][1] = __expf(S[nb][1] - mn0);
            S[nb][2] = __expf(S[nb][2] - mn1);
            S[nb][3] = __expf(S[nb][3] - mn1);
            ts0 += S[nb][0] + S[nb][1];
            ts1 += S[nb][2] + S[nb][3];
        }
        ts0 += __shfl_xor_sync(0xffffffffu, ts0, 1);
        ts0 += __shfl_xor_sync(0xffffffffu, ts0, 2);
        ts1 += __shfl_xor_sync(0xffffffffu, ts1, 1);
        ts1 += __shfl_xor_sync(0xffffffffu, ts1, 2);
        l0 = l0 * sc0 + ts0;
        l1 = l1 * sc1 + ts1;
        m0 = mn0; m1 = mn1;
        #pragma unroll
        for (int nb = 0; nb < 8; nb++) {
            Oa[nb][0] *= sc0; Oa[nb][1] *= sc0;
            Oa[nb][2] *= sc1; Oa[nb][3] *= sc1;
        }
        // O += P @ V (ldmatrix.trans on V rows)
        #pragma unroll
        for (int ks = 0; ks < 4; ks++) {
            uint32_t ap[4];
            ap[0] = h2u(__floats2half2_rn(S[2 * ks][0], S[2 * ks][1]));
            ap[1] = h2u(__floats2half2_rn(S[2 * ks][2], S[2 * ks][3]));
            ap[2] = h2u(__floats2half2_rn(S[2 * ks + 1][0], S[2 * ks + 1][1]));
            ap[3] = h2u(__floats2half2_rn(S[2 * ks + 1][2], S[2 * ks + 1][3]));
            int krow = kt * 64 + ks * 16 + vRowLoc;
            uint32_t rbase = sV + (uint32_t)krow * 128;
            uint32_t rx = (uint32_t)(krow & 7);
            #pragma unroll
            for (int dp = 0; dp < 4; dp++) {
                uint32_t cg = (uint32_t)(dp * 2) + lk;
                uint32_t vr[4];
                ldsm4t(vr, rbase + ((cg ^ rx) << 4));
                uint32_t b0[2] = {vr[0], vr[1]};
                uint32_t b1[2] = {vr[2], vr[3]};
                mma_f16(Oa[2 * dp], ap, b0);
                mma_f16(Oa[2 * dp + 1], ap, b1);
            }
        }
    }

    float inv0 = 1.0f / l0, inv1 = 1.0f / l1;
    __half* op = o + ((size_t)(b * TT + qbase + g) * CC + h * HS);
    __half* op1 = op + 8 * CC;
    #pragma unroll
    for (int nb = 0; nb < 8; nb++) {
        *(__half2*)&op[nb * 8 + 2 * tg]  = __floats2half2_rn(Oa[nb][0] * inv0, Oa[nb][1] * inv0);
        *(__half2*)&op1[nb * 8 + 2 * tg] = __floats2half2_rn(Oa[nb][2] * inv1, Oa[nb][3] * inv1);
    }
}

// ---------------- PDL launch helper ----------------
template <typename F, typename... Args>
static inline void launch_pdl(F kern, dim3 grid, dim3 block, size_t smem, Args... args) {
    cudaLaunchConfig_t cfg = {};
    cfg.gridDim = grid;
    cfg.blockDim = block;
    cfg.dynamicSmemBytes = smem;
    cfg.stream = 0;
    cudaLaunchAttribute attr[1];
    attr[0].id = cudaLaunchAttributeProgrammaticStreamSerialization;
    attr[0].val.programmaticStreamSerializationAllowed = 1;
    cfg.attrs = attr;
    cfg.numAttrs = 1;
    cudaLaunchKernelEx(&cfg, kern, args...);
}

// ---------------- launch ----------------
extern "C" void kernel_launch(void* const* d_in, const int* in_sizes, int n_in,
                              void* d_out, int out_size) {
    const float* x     = (const float*)d_in[0];
    const float* ln1w  = (const float*)d_in[1];
    const float* ln1b  = (const float*)d_in[2];
    const float* Wq    = (const float*)d_in[3];
    const float* bq    = (const float*)d_in[4];
    const float* Wk    = (const float*)d_in[5];
    const float* bk    = (const float*)d_in[6];
    const float* Wv    = (const float*)d_in[7];
    const float* bv    = (const float*)d_in[8];
    const float* Wproj = (const float*)d_in[9];
    const float* bproj = (const float*)d_in[10];
    const float* ln2w  = (const float*)d_in[11];
    const float* ln2b  = (const float*)d_in[12];
    const float* W1    = (const float*)d_in[13];
    const float* b1    = (const float*)d_in[14];
    const float* W2    = (const float*)d_in[15];
    const float* b2    = (const float*)d_in[16];
    float* out = (float*)d_out;

    __half *h, *qkvh, *o, *f1, *wqkvT, *wprojT, *w1T, *w2T;
    float *x1, *bqkv;
    cudaGetSymbolAddress((void**)&h, g_h);
    cudaGetSymbolAddress((void**)&qkvh, g_qkvh);
    cudaGetSymbolAddress((void**)&o, g_o);
    cudaGetSymbolAddress((void**)&x1, g_x1);
    cudaGetSymbolAddress((void**)&f1, g_f1);
    cudaGetSymbolAddress((void**)&wqkvT, g_WqkvT);
    cudaGetSymbolAddress((void**)&wprojT, g_WprojT);
    cudaGetSymbolAddress((void**)&w1T, g_W1T);
    cudaGetSymbolAddress((void**)&w2T, g_W2T);
    cudaGetSymbolAddress((void**)&bqkv, g_bqkv);

    cudaFuncSetAttribute(attn_mma, cudaFuncAttributeMaxDynamicSharedMemorySize, ATT_SMEM);
    cudaFuncSetAttribute(mma_gemm16<0, 1>, cudaFuncAttributeMaxDynamicSharedMemorySize, SMEM_TOTAL_G);
    cudaFuncSetAttribute(mma_gemm16<1, 0>, cudaFuncAttributeMaxDynamicSharedMemorySize, SMEM_TOTAL_G);
    cudaFuncSetAttribute(mma_gemm16<2, 1>, cudaFuncAttributeMaxDynamicSharedMemorySize, SMEM_TOTAL_G);

    // fused weight pack + LN1 (independent work, one kernel)
    pack_ln_kernel<<<PACK_BLOCKS + LN_BLOCKS, 256>>>(Wq, Wk, Wv, bq, bk, bv,
                                                     Wproj, W1, W2, x, ln1w, ln1b, h);
    // QKV GEMM (half out)  [PDL]
    launch_pdl(mma_gemm16<0, 1>, dim3(NQKV / 128, MM / 128), dim3(256), (size_t)SMEM_TOTAL_G,
               (const __half*)h, (const __half*)wqkvT, (const float*)bqkv,
               (const float*)nullptr, (void*)qkvh, MM, NQKV, CC);
    // flash attention  [PDL]
    launch_pdl(attn_mma, dim3(BB * HH * 2), dim3(256), (size_t)ATT_SMEM,
               (const __half*)qkvh, (__half*)o);
    // proj + residual (-> f32 x1)  [PDL]
    launch_pdl(mma_gemm16<1, 0>, dim3(CC / 128, MM / 128), dim3(256), (size_t)SMEM_TOTAL_G,
               (const __half*)o, (const __half*)wprojT, (const float*)bproj,
               (const float*)x, (void*)x1, MM, CC, CC);
    // LN2 (-> half)  [PDL]
    launch_pdl(ln_kernel, dim3(MM / 8), dim3(256), (size_t)0,
               (const float*)x1, (const float*)ln2w, (const float*)ln2b, (__half*)h);
    // FFN1 + GELU (-> half f1)  [PDL]
    launch_pdl(mma_gemm16<2, 1>, dim3(CF / 128, MM / 128), dim3(256), (size_t)SMEM_TOTAL_G,
               (const __half*)h, (const __half*)w1T, (const float*)b1,
               (const float*)nullptr, (void*)f1, MM, CF, CC);
    // FFN2 + residual (-> f32 out)  [PDL]
    launch_pdl(mma_gemm16<1, 0>, dim3(CC / 128, MM / 128), dim3(256), (size_t)SMEM_TOTAL_G,
               (const __half*)f1, (const __half*)w2T, (const float*)b2,
               (const float*)x1, (void*)out, MM, CC, CF);
}